// round 15
// baseline (speedup 1.0000x reference)
#include <cuda_runtime.h>
#include <cstdint>

#define L2E 1.4426950408889634f
typedef unsigned long long ull;

// Scratch (static device globals — no runtime allocation)
__device__ float g_P1[4 * 64 * 512];     // split-K partials of f@W1
__device__ float g_P2[8 * 64 * 1024];    // split-K partials of relu(h1)@W2
__device__ float g_P3[16 * 64 * 512];    // split-K partials of relu(h2)@W3

// Grid-barrier state (returns to all-zero at end of every launch)
__device__ unsigned g_cnt[3]  = {0, 0, 0};
__device__ unsigned g_exit[3] = {0, 0, 0};

// ---- packed f32x2 helpers ---------------------------------------------------
__device__ __forceinline__ ull pk2(float lo, float hi) {
    ull r; asm("mov.b64 %0, {%1, %2};" : "=l"(r) : "f"(lo), "f"(hi)); return r;
}
__device__ __forceinline__ void upk2(float& lo, float& hi, ull v) {
    asm("mov.b64 {%0, %1}, %2;" : "=f"(lo), "=f"(hi) : "l"(v));
}
__device__ __forceinline__ ull fma2(ull a, ull b, ull c) {
    ull d; asm("fma.rn.f32x2 %0, %1, %2, %3;" : "=l"(d) : "l"(a), "l"(b), "l"(c)); return d;
}
__device__ __forceinline__ ull mul2(ull a, ull b) {
    ull d; asm("mul.rn.f32x2 %0, %1, %2;" : "=l"(d) : "l"(a), "l"(b)); return d;
}
__device__ __forceinline__ ull add2(ull a, ull b) {
    ull d; asm("add.rn.f32x2 %0, %1, %2;" : "=l"(d) : "l"(a), "l"(b)); return d;
}

// ---- software grid barrier (256 blocks, <=2/SM co-resident) -----------------
__device__ __forceinline__ void grid_bar(int i) {
    __syncthreads();
    if (threadIdx.x == 0) {
        __threadfence();
        atomicAdd(&g_cnt[i], 1u);
        while (*(volatile unsigned*)&g_cnt[i] < 256u) __nanosleep(40);
        __threadfence();
        unsigned e = atomicAdd(&g_exit[i], 1u);
        if (e == 255u) {                 // last exiter: everyone left the spin
            g_cnt[i] = 0; __threadfence(); g_exit[i] = 0;
        }
    }
    __syncthreads();
}

// ---------------------------------------------------------------------------
// GEMM tile (unchanged from R14 — known-good).
// ---------------------------------------------------------------------------
__device__ void gemm_tile(
    float* As, float (*Ws)[32][32],
    const float* __restrict__ A,
    const float* __restrict__ Aparts, int nparts,
    const float* __restrict__ abias,
    int K_full, int KS,
    const float* __restrict__ W, int N,
    int n0, int k0,
    float* __restrict__ out)
{
    const int tid = threadIdx.x;

    const int KQ4 = KS / 4;
    for (int f = tid; f < 64 * KQ4; f += 256) {
        int m = f / KQ4, kq = f - m * KQ4;
        int k = k0 + 4 * kq;
        float4 v;
        if (A) {
            v = *(const float4*)(A + (size_t)m * K_full + k);
        } else {
            v = *(const float4*)(abias + k);
            for (int p = 0; p < nparts; p++) {
                float4 w = *(const float4*)(Aparts + (size_t)p * 64 * K_full
                                            + (size_t)m * K_full + k);
                v.x += w.x; v.y += w.y; v.z += w.z; v.w += w.w;
            }
            v.x = fmaxf(v.x, 0.f); v.y = fmaxf(v.y, 0.f);
            v.z = fmaxf(v.z, 0.f); v.w = fmaxf(v.w, 0.f);
        }
        *(float4*)&As[m * KS + 4 * kq] = v;
    }

    const int iw = tid >> 3, nn = (tid & 7) * 4;
    {
        float4 w = *(const float4*)(W + (size_t)(k0 + iw) * N + n0 + nn);
        *(float4*)&Ws[0][iw][nn] = w;
    }
    __syncthreads();

    const int n  = tid & 31;
    const int mb = (tid >> 5) * 8;
    ull acc2[8] = {0,0,0,0,0,0,0,0};

    const int NC = KS / 32;
    for (int c = 0; c < NC; c++) {
        if (c + 1 < NC) {
            float4 w = *(const float4*)(W + (size_t)(k0 + (c+1)*32 + iw) * N + n0 + nn);
            *(float4*)&Ws[(c + 1) & 1][iw][nn] = w;
        }
        const float* wsb = &Ws[c & 1][0][0];
        const int kc = c * 32;
        #pragma unroll
        for (int k = 0; k < 32; k += 4) {
            float w0 = wsb[(k+0)*32 + n], w1 = wsb[(k+1)*32 + n];
            float w2 = wsb[(k+2)*32 + n], w3 = wsb[(k+3)*32 + n];
            ull wA = pk2(w0, w1), wB = pk2(w2, w3);
            #pragma unroll
            for (int q = 0; q < 8; q++) {
                ulonglong2 av = *(const ulonglong2*)&As[(mb + q) * KS + kc + k];
                acc2[q] = fma2(av.x, wA, acc2[q]);
                acc2[q] = fma2(av.y, wB, acc2[q]);
            }
        }
        __syncthreads();
    }

    #pragma unroll
    for (int q = 0; q < 8; q++) {
        float lo, hi; upk2(lo, hi, acc2[q]);
        out[(size_t)(mb + q) * N + n0 + n] = lo + hi;
    }
}

// ---------------------------------------------------------------------------
// MLP: 3 phases in one persistent launch (grid 256, 2 barriers). Unchanged.
// ---------------------------------------------------------------------------
__global__ void __launch_bounds__(256, 2) mlp_fused(
    const float* __restrict__ f,
    const float* __restrict__ W1, const float* __restrict__ b1,
    const float* __restrict__ W2, const float* __restrict__ b2,
    const float* __restrict__ W3)
{
    __shared__ float As[64 * 64];
    __shared__ float Ws[2][32][32];

    const int bid = blockIdx.x;

    if (bid < 64) {
        int n0 = (bid & 15) * 32, ks = bid >> 4;
        gemm_tile(As, Ws, f, nullptr, 0, nullptr, 128, 32, W1, 512,
                  n0, ks * 32, g_P1 + (size_t)ks * 64 * 512);
    }
    grid_bar(0);

    {
        int n0 = (bid & 31) * 32, ks = bid >> 5;
        gemm_tile(As, Ws, nullptr, g_P1, 4, b1, 512, 64, W2, 1024,
                  n0, ks * 64, g_P2 + (size_t)ks * 64 * 1024);
    }
    grid_bar(1);

    {
        int n0 = (bid & 15) * 32, ks = bid >> 4;
        gemm_tile(As, Ws, nullptr, g_P2, 8, b2, 1024, 64, W3, 512,
                  n0, ks * 64, g_P3 + (size_t)ks * 64 * 512);
    }
}

// ---------------------------------------------------------------------------
// Einsum: E=4 elems/thread, 128 thr, grid (8,64). cos computed as packed
// f32x2 polynomial (magic-rint range reduction + even Taylor to y^14) —
// MUFU now carries only ex2 (4/iter instead of 8-12).
// ---------------------------------------------------------------------------
__global__ void __launch_bounds__(128) subspace_einsum(
    const float* __restrict__ t,
    const float* __restrict__ mu, const float* __restrict__ alpha,
    const float* __restrict__ beta, const float* __restrict__ gamma,
    const float* __restrict__ b3,
    float* __restrict__ out)
{
    __shared__ float s_p[64], s_q[64], s_r[64], s_be[64], s_ga[64];
    __shared__ float4 s_we[64], s_wo[64];

    const int tid = threadIdx.x;
    const int b   = blockIdx.y;
    const int sc  = blockIdx.x;

    if (tid < 64) {
        float al = alpha[tid], m = mu[tid];
        float a2 = al * al * L2E;
        s_p[tid]  = -a2;
        s_q[tid]  = 2.f * a2 * m;
        s_r[tid]  = -a2 * m * m;
        s_be[tid] = beta[tid];
        s_ga[tid] = gamma[tid];
    }
    for (int j = tid; j < 512; j += 128) {
        float v = b3[j];
        #pragma unroll
        for (int p = 0; p < 16; p++)
            v += g_P3[(size_t)p * 64 * 512 + (size_t)b * 512 + j];
        int row = j >> 2, r = j & 3;
        int nb = row & 63;
        float* dst = (row < 64) ? (float*)&s_we[nb] : (float*)&s_wo[nb];
        dst[r] = v;
    }
    __syncthreads();

    // packed constants for cos poly (uniform across threads)
    const ull INV2PI = pk2(0.15915494309189535f, 0.15915494309189535f);
    const ull MAGIC  = pk2(12582912.0f, 12582912.0f);       // 1.5 * 2^23
    const ull NMAGIC = pk2(-12582912.0f, -12582912.0f);
    const ull N2PI   = pk2(-6.283185307179586f, -6.283185307179586f);
    const ull C14 = pk2(1.1470745598e-11f, 1.1470745598e-11f);
    const ull C12 = pk2(-2.0876756988e-09f, -2.0876756988e-09f);
    const ull C10 = pk2(2.7557319224e-07f, 2.7557319224e-07f);
    const ull C8  = pk2(-2.4801587302e-05f, -2.4801587302e-05f);
    const ull C6  = pk2(1.3888888889e-03f, 1.3888888889e-03f);
    const ull C4  = pk2(-4.1666666667e-02f, -4.1666666667e-02f);
    const ull C2  = pk2(0.5f, 0.5f);
    const ull C0  = pk2(1.0f, 1.0f);
    // poly computes: 1 - y2*(C2 - y2*(C4n...)) form? We evaluate:
    //   cp = (((((C14*y2 + C12n)*y2 + C10)... with alternating signs folded in:
    // cos(y) = C0 + y2*(-C2 + y2*(-C4n ...)). To keep one Horner chain we fold
    // signs into the constants directly below (Cx above already signed so that
    // cp = fma(...(fma(C14, y2, C12), y2, C10)...) ends with fma(cp, y2n, C0)
    // where y2n = -y2? Simpler: constants alternate sign naturally:
    //   cos = 1 - y2/2 + y4/24 - ... ; Horner in y2 with signed Taylor coeffs.
    // Signed set: a14=-1/14!? We use: cp = fma(A14, y2, A12); ... A0 = 1.
    const ull A14 = pk2(-1.1470745598e-11f, -1.1470745598e-11f);
    const ull A12 = pk2(2.0876756988e-09f, 2.0876756988e-09f);
    const ull A10 = pk2(-2.7557319224e-07f, -2.7557319224e-07f);
    const ull A8  = pk2(2.4801587302e-05f, 2.4801587302e-05f);
    const ull A6  = pk2(-1.3888888889e-03f, -1.3888888889e-03f);
    const ull A4  = pk2(4.1666666667e-02f, 4.1666666667e-02f);
    const ull A2  = pk2(-0.5f, -0.5f);
    const ull A0  = pk2(1.0f, 1.0f);
    (void)C14; (void)C12; (void)C10; (void)C8; (void)C6; (void)C4; (void)C2; (void)C0;

    const float* tb = t + (size_t)b * 4096;
    const int s0 = sc * 512 + tid;
    float tA0 = tb[s0],       tA1 = tb[s0 + 128];
    float tB0 = tb[s0 + 256], tB1 = tb[s0 + 384];
    const ull ttA = pk2(tA0, tA1), tqA = pk2(tA0 * tA0, tA1 * tA1);
    const ull ttB = pk2(tB0, tB1), tqB = pk2(tB0 * tB0, tB1 * tB1);

    ull acc[16];
    #pragma unroll
    for (int j = 0; j < 16; j++) acc[j] = 0ull;

    #pragma unroll 4
    for (int nb = 0; nb < 64; nb++) {
        float p = s_p[nb], q = s_q[nb], r = s_r[nb];
        float be = s_be[nb], ga = s_ga[nb];
        ull pp = pk2(p, p), qq = pk2(q, q), rr = pk2(r, r);
        ull bb = pk2(be, be), gg = pk2(ga, ga);
        ulonglong2 we = *(const ulonglong2*)&s_we[nb];
        ulonglong2 wo = *(const ulonglong2*)&s_wo[nb];

        #pragma unroll
        for (int P = 0; P < 2; P++) {
            const ull tt = P ? ttB : ttA;
            const ull tq = P ? tqB : tqA;

            // exp term (MUFU ex2 only)
            ull a = fma2(pp, tq, fma2(qq, tt, rr));
            float a0, a1; upk2(a0, a1, a);
            float e0, e1;
            asm("ex2.approx.f32 %0, %1;" : "=f"(e0) : "f"(a0));
            asm("ex2.approx.f32 %0, %1;" : "=f"(e1) : "f"(a1));
            ull ee = pk2(e0, e1);

            // cos term: packed range reduction + even Taylor (FMA pipe)
            ull xr = fma2(bb, tt, gg);
            ull nm = fma2(xr, INV2PI, MAGIC);
            ull nn = add2(nm, NMAGIC);
            ull y  = fma2(nn, N2PI, xr);
            ull y2 = mul2(y, y);
            ull cp = fma2(A14, y2, A12);
            cp = fma2(cp, y2, A10);
            cp = fma2(cp, y2, A8);
            cp = fma2(cp, y2, A6);
            cp = fma2(cp, y2, A4);
            cp = fma2(cp, y2, A2);
            cp = fma2(cp, y2, A0);

            ull h = mul2(ee, cp);
            float h0, h1; upk2(h0, h1, h);
            ull hh0 = pk2(h0, h0), hh1 = pk2(h1, h1);

            ull* ac = acc + P * 8;
            ac[0] = fma2(hh0, we.x, ac[0]);
            ac[1] = fma2(hh0, we.y, ac[1]);
            ac[2] = fma2(hh0, wo.x, ac[2]);
            ac[3] = fma2(hh0, wo.y, ac[3]);
            ac[4] = fma2(hh1, we.x, ac[4]);
            ac[5] = fma2(hh1, we.y, ac[5]);
            ac[6] = fma2(hh1, wo.x, ac[6]);
            ac[7] = fma2(hh1, wo.y, ac[7]);
        }
    }

    float* ob = out + (size_t)b * 32768;
    #pragma unroll
    for (int P = 0; P < 2; P++) {
        const ull* ac = acc + P * 8;
        int sL = s0 + P * 256, sH = sL + 128;
        float x0, x1, x2, x3;
        upk2(x0, x1, ac[0]); upk2(x2, x3, ac[1]);
        ((float4*)(ob + 8 * (size_t)sL))[0] = make_float4(x0, x1, x2, x3);
        upk2(x0, x1, ac[2]); upk2(x2, x3, ac[3]);
        ((float4*)(ob + 8 * (size_t)sL))[1] = make_float4(x0, x1, x2, x3);
        upk2(x0, x1, ac[4]); upk2(x2, x3, ac[5]);
        ((float4*)(ob + 8 * (size_t)sH))[0] = make_float4(x0, x1, x2, x3);
        upk2(x0, x1, ac[6]); upk2(x2, x3, ac[7]);
        ((float4*)(ob + 8 * (size_t)sH))[1] = make_float4(x0, x1, x2, x3);
    }
}

extern "C" void kernel_launch(void* const* d_in, const int* in_sizes, int n_in,
                              void* d_out, int out_size) {
    const float* f     = (const float*)d_in[0];
    const float* t     = (const float*)d_in[1];
    const float* W1    = (const float*)d_in[2];
    const float* b1    = (const float*)d_in[3];
    const float* W2    = (const float*)d_in[4];
    const float* b2    = (const float*)d_in[5];
    const float* W3    = (const float*)d_in[6];
    const float* b3    = (const float*)d_in[7];
    const float* mu    = (const float*)d_in[8];
    const float* alpha = (const float*)d_in[9];
    const float* beta  = (const float*)d_in[10];
    const float* gamma = (const float*)d_in[11];
    float* out = (float*)d_out;

    mlp_fused<<<256, 256>>>(f, W1, b1, W2, b2, W3);
    subspace_einsum<<<dim3(8, 64), 128>>>(t, mu, alpha, beta, gamma, b3, out);
}